// round 1
// baseline (speedup 1.0000x reference)
#include <cuda_runtime.h>
#include <cuda_bf16.h>
#include <math.h>

// ---------------- problem constants ----------------
#define T_SEQ   2048
#define D_MODEL 3072
#define N_HEADS 16
#define K_HEADS 8
#define HDIM    256
#define WINDOW  1024
#define SOFT_CAP 50.0f
#define EPS 1e-6f

// ---------------- scratch (static device globals; no runtime allocs) ----------------
__device__ float g_q  [(size_t)T_SEQ * N_HEADS * HDIM];   // [t][n][h]
__device__ float g_kv [(size_t)T_SEQ * 16 * HDIM];        // [t][c*8+kh][h]; c=0 -> K, c=1 -> V
__device__ float g_enc[(size_t)T_SEQ * N_HEADS * HDIM];   // [t][n][h]

// ---------------- generic tiled fp32 GEMM ----------------
// C[t, head*NC + h] = sum_d A[t,d] * W[head][d,h]
// block tile 128x64, K-tile 16, 256 threads, per-thread 8x4
template<int K, int NC>
__device__ __forceinline__ void gemm_body(const float* __restrict__ A,
                                          const float* __restrict__ W,
                                          float* __restrict__ out,
                                          int out_rowstride)
{
    const int head = blockIdx.z;
    const float* Wh = W + (size_t)head * K * NC;
    const int m0 = blockIdx.y * 128;
    const int n0 = blockIdx.x * 64;

    __shared__ float As[16][132];   // transposed A tile, padded (conflict-light, f4-aligned)
    __shared__ float Bs[16][64];

    const int tid = threadIdx.x;
    const int ty = tid >> 4;        // 0..15 (row group)
    const int tx = tid & 15;        // 0..15 (col group)

    float acc[8][4];
    #pragma unroll
    for (int i = 0; i < 8; i++)
        #pragma unroll
        for (int j = 0; j < 4; j++) acc[i][j] = 0.f;

    for (int k0 = 0; k0 < K; k0 += 16) {
        // load A tile (128x16) transposed into As
        #pragma unroll
        for (int l = 0; l < 2; l++) {
            int idx = tid + l * 256;          // 0..511 float4s
            int r  = idx >> 2;                // 0..127
            int kq = (idx & 3) << 2;          // 0,4,8,12
            float4 va = *reinterpret_cast<const float4*>(&A[(size_t)(m0 + r) * K + k0 + kq]);
            As[kq + 0][r] = va.x;
            As[kq + 1][r] = va.y;
            As[kq + 2][r] = va.z;
            As[kq + 3][r] = va.w;
        }
        // load B tile (16x64)
        {
            int r = tid >> 4;                 // 0..15
            int c = (tid & 15) << 2;          // 0..60
            *reinterpret_cast<float4*>(&Bs[r][c]) =
                *reinterpret_cast<const float4*>(&Wh[(size_t)(k0 + r) * NC + n0 + c]);
        }
        __syncthreads();

        #pragma unroll
        for (int kk = 0; kk < 16; kk++) {
            float4 a0 = *reinterpret_cast<const float4*>(&As[kk][ty * 8]);
            float4 a1 = *reinterpret_cast<const float4*>(&As[kk][ty * 8 + 4]);
            float4 b0 = *reinterpret_cast<const float4*>(&Bs[kk][tx * 4]);
            float a[8] = {a0.x, a0.y, a0.z, a0.w, a1.x, a1.y, a1.z, a1.w};
            float b[4] = {b0.x, b0.y, b0.z, b0.w};
            #pragma unroll
            for (int i = 0; i < 8; i++)
                #pragma unroll
                for (int j = 0; j < 4; j++)
                    acc[i][j] = fmaf(a[i], b[j], acc[i][j]);
        }
        __syncthreads();
    }

    #pragma unroll
    for (int i = 0; i < 8; i++) {
        int t = m0 + ty * 8 + i;
        float4 v = make_float4(acc[i][0], acc[i][1], acc[i][2], acc[i][3]);
        *reinterpret_cast<float4*>(&out[(size_t)t * out_rowstride + head * NC + n0 + tx * 4]) = v;
    }
}

__global__ __launch_bounds__(256) void gemm_q_kernel(const float* __restrict__ x,
                                                     const float* __restrict__ w)
{ gemm_body<D_MODEL, HDIM>(x, w, g_q, N_HEADS * HDIM); }

__global__ __launch_bounds__(256) void gemm_kv_kernel(const float* __restrict__ x,
                                                      const float* __restrict__ w)
{ gemm_body<D_MODEL, HDIM>(x, w, g_kv, 16 * HDIM); }

__global__ __launch_bounds__(256) void gemm_out_kernel(const float* __restrict__ w,
                                                       float* __restrict__ out)
{ gemm_body<N_HEADS * HDIM, D_MODEL>(g_enc, w, out, D_MODEL); }

// ---------------- RMS-norm (+scale) (+RoPE) : warp per 256-wide row ----------------
__device__ __forceinline__ void rope_apply(float v[8], int lane, int pos)
{
    #pragma unroll
    for (int j = 0; j < 4; j++) {
        int hh = lane + 32 * j;                       // 0..127 (first half index)
        float ts = powf(10000.0f, (float)hh * (1.0f / 128.0f));
        float arg = (float)pos / ts;
        float sn, cs;
        sincosf(arg, &sn, &cs);
        float f = v[j], s = v[j + 4];
        v[j]     = f * cs - s * sn;
        v[j + 4] = s * cs + f * sn;
    }
}

__global__ __launch_bounds__(256) void norm_rope_q_kernel(const float* __restrict__ qscale,
                                                          const int* __restrict__ segpos)
{
    int row  = blockIdx.x * 8 + (threadIdx.x >> 5);   // 0 .. T*N-1
    int lane = threadIdx.x & 31;
    int t = row >> 4;                                  // N_HEADS = 16
    float* p = g_q + (size_t)row * HDIM;

    float v[8]; float ss = 0.f;
    #pragma unroll
    for (int j = 0; j < 8; j++) { v[j] = p[lane + 32 * j]; ss += v[j] * v[j]; }
    #pragma unroll
    for (int o = 16; o > 0; o >>= 1) ss += __shfl_xor_sync(0xffffffffu, ss, o);
    float rstd = rsqrtf(ss * (1.0f / 256.0f) + EPS);

    #pragma unroll
    for (int j = 0; j < 8; j++) {
        int h = lane + 32 * j;
        v[j] = v[j] * rstd * (1.0f + qscale[h]);
    }
    rope_apply(v, lane, segpos[t]);
    #pragma unroll
    for (int j = 0; j < 8; j++) p[lane + 32 * j] = v[j];
}

__global__ __launch_bounds__(256) void norm_rope_kv_kernel(const float* __restrict__ kscale,
                                                           const int* __restrict__ segpos)
{
    int row  = blockIdx.x * 8 + (threadIdx.x >> 5);   // 0 .. T*16-1
    int lane = threadIdx.x & 31;
    int t    = row >> 4;
    int head = row & 15;                               // <8: K head; >=8: V head
    float* p = g_kv + (size_t)row * HDIM;

    float v[8]; float ss = 0.f;
    #pragma unroll
    for (int j = 0; j < 8; j++) { v[j] = p[lane + 32 * j]; ss += v[j] * v[j]; }
    #pragma unroll
    for (int o = 16; o > 0; o >>= 1) ss += __shfl_xor_sync(0xffffffffu, ss, o);
    float rstd = rsqrtf(ss * (1.0f / 256.0f) + EPS);

    if (head < 8) {
        #pragma unroll
        for (int j = 0; j < 8; j++) {
            int h = lane + 32 * j;
            v[j] = v[j] * rstd * (1.0f + kscale[h]);
        }
        rope_apply(v, lane, segpos[t]);
    } else {
        #pragma unroll
        for (int j = 0; j < 8; j++) v[j] *= rstd;
    }
    #pragma unroll
    for (int j = 0; j < 8; j++) p[lane + 32 * j] = v[j];
}

// ---------------- flash attention: 64 queries x 1 head per block, 32-key chunks ----------------
// smem (floats): qs [64][256] | ks [32][260] | vs [32][260] | ps [64][32]
#define ATTN_SMEM_FLOATS (64 * 256 + 32 * 260 + 32 * 260 + 64 * 32)

__global__ __launch_bounds__(256, 1) void attn_kernel()
{
    extern __shared__ float sm[];
    float* qs = sm;                 // row stride 256
    float* ks = sm + 64 * 256;      // row stride 260 (padded)
    float* vs = ks + 32 * 260;      // row stride 260 (padded)
    float* ps = vs + 32 * 260;      // row stride 32

    const int tile = blockIdx.x;
    const int n    = blockIdx.y;
    const int kh   = n >> 1;        // G = N/K = 2
    const int t0   = tile * 64;
    const int tid  = threadIdx.x;
    const int rg   = tid >> 4;      // 0..15  -> rows rg*4 .. +3
    const int cg   = tid & 15;      // 0..15  -> score cols {cg, cg+16}; o cols {cg*4 + jj*64}
    const int r0   = rg << 2;

    // load q tile
    #pragma unroll
    for (int l = 0; l < 16; l++) {
        int idx = tid + l * 256;
        int r = idx >> 6;
        int c = (idx & 63) << 2;
        *reinterpret_cast<float4*>(&qs[r * 256 + c]) =
            *reinterpret_cast<const float4*>(&g_q[((size_t)(t0 + r) * 16 + n) * 256 + c]);
    }

    float4 o[4][4];
    #pragma unroll
    for (int i = 0; i < 4; i++)
        #pragma unroll
        for (int j = 0; j < 4; j++) o[i][j] = make_float4(0.f, 0.f, 0.f, 0.f);
    float mrow[4], lrow[4];
    #pragma unroll
    for (int i = 0; i < 4; i++) { mrow[i] = -1e30f; lrow[i] = 0.f; }

    int s_lo = t0 - (WINDOW - 1); if (s_lo < 0) s_lo = 0; s_lo &= ~31;
    const int s_hi = t0 + 63;

    __syncthreads();  // q visible

    for (int sc0 = s_lo; sc0 <= s_hi; sc0 += 32) {
        // load K and V chunk
        #pragma unroll
        for (int l = 0; l < 8; l++) {
            int idx = tid + l * 256;
            int r = idx >> 6;
            int c = (idx & 63) << 2;
            *reinterpret_cast<float4*>(&ks[r * 260 + c]) =
                *reinterpret_cast<const float4*>(&g_kv[((size_t)(sc0 + r) * 16 + kh) * 256 + c]);
            *reinterpret_cast<float4*>(&vs[r * 260 + c]) =
                *reinterpret_cast<const float4*>(&g_kv[((size_t)(sc0 + r) * 16 + 8 + kh) * 256 + c]);
        }
        __syncthreads();

        // scores: 4 rows x 2 cols per thread; cols = cg and cg+16
        float s[4][2];
        #pragma unroll
        for (int i = 0; i < 4; i++) { s[i][0] = 0.f; s[i][1] = 0.f; }

        #pragma unroll 4
        for (int k = 0; k < 256; k += 4) {
            float4 b0 = *reinterpret_cast<const float4*>(&ks[cg * 260 + k]);
            float4 b1 = *reinterpret_cast<const float4*>(&ks[(cg + 16) * 260 + k]);
            #pragma unroll
            for (int i = 0; i < 4; i++) {
                float4 a = *reinterpret_cast<const float4*>(&qs[(r0 + i) * 256 + k]);
                s[i][0] += a.x * b0.x + a.y * b0.y + a.z * b0.z + a.w * b0.w;
                s[i][1] += a.x * b1.x + a.y * b1.y + a.z * b1.z + a.w * b1.w;
            }
        }

        // soft-cap + causal/sliding mask
        #pragma unroll
        for (int i = 0; i < 4; i++) {
            int tq = t0 + r0 + i;
            #pragma unroll
            for (int j = 0; j < 2; j++) {
                int sk = sc0 + cg + 16 * j;
                float val = tanhf(s[i][j] * (1.0f / SOFT_CAP)) * SOFT_CAP;
                bool ok = (sk <= tq) && (sk > tq - WINDOW);
                s[i][j] = ok ? val : -1e30f;
            }
        }

        // online softmax per row (reduce across the 16 lanes sharing the row group)
        #pragma unroll
        for (int i = 0; i < 4; i++) {
            float mx = fmaxf(s[i][0], s[i][1]);
            #pragma unroll
            for (int off = 8; off > 0; off >>= 1)
                mx = fmaxf(mx, __shfl_xor_sync(0xffffffffu, mx, off));
            float m_new = fmaxf(mrow[i], mx);
            float alpha = __expf(mrow[i] - m_new);
            float p0 = __expf(s[i][0] - m_new);
            float p1 = __expf(s[i][1] - m_new);
            float rs = p0 + p1;
            #pragma unroll
            for (int off = 8; off > 0; off >>= 1)
                rs += __shfl_xor_sync(0xffffffffu, rs, off);
            lrow[i] = lrow[i] * alpha + rs;
            mrow[i] = m_new;
            #pragma unroll
            for (int jj = 0; jj < 4; jj++) {
                o[i][jj].x *= alpha; o[i][jj].y *= alpha;
                o[i][jj].z *= alpha; o[i][jj].w *= alpha;
            }
            ps[(r0 + i) * 32 + cg]      = p0;
            ps[(r0 + i) * 32 + cg + 16] = p1;
        }
        __syncthreads();

        // PV: o[4 rows][16 cols] += p @ v
        #pragma unroll 4
        for (int sk = 0; sk < 32; sk++) {
            float p[4];
            #pragma unroll
            for (int i = 0; i < 4; i++) p[i] = ps[(r0 + i) * 32 + sk];
            #pragma unroll
            for (int jj = 0; jj < 4; jj++) {
                float4 v = *reinterpret_cast<const float4*>(&vs[sk * 260 + cg * 4 + jj * 64]);
                #pragma unroll
                for (int i = 0; i < 4; i++) {
                    o[i][jj].x = fmaf(p[i], v.x, o[i][jj].x);
                    o[i][jj].y = fmaf(p[i], v.y, o[i][jj].y);
                    o[i][jj].z = fmaf(p[i], v.z, o[i][jj].z);
                    o[i][jj].w = fmaf(p[i], v.w, o[i][jj].w);
                }
            }
        }
        __syncthreads();
    }

    // normalize and write enc
    #pragma unroll
    for (int i = 0; i < 4; i++) {
        float inv = 1.0f / lrow[i];
        int t = t0 + r0 + i;
        #pragma unroll
        for (int jj = 0; jj < 4; jj++) {
            float4 v = o[i][jj];
            v.x *= inv; v.y *= inv; v.z *= inv; v.w *= inv;
            *reinterpret_cast<float4*>(&g_enc[((size_t)t * 16 + n) * 256 + cg * 4 + jj * 64]) = v;
        }
    }
}

// ---------------- launch ----------------
extern "C" void kernel_launch(void* const* d_in, const int* in_sizes, int n_in,
                              void* d_out, int out_size)
{
    const float* x       = (const float*)d_in[0];
    const int*   segpos  = (const int*)  d_in[1];
    // d_in[2] = attn_mask (causal tril) — realized analytically in-kernel
    const float* w_q     = (const float*)d_in[3];
    const float* w_kv    = (const float*)d_in[4];
    const float* w_out   = (const float*)d_in[5];
    const float* q_scale = (const float*)d_in[6];
    const float* k_scale = (const float*)d_in[7];
    float*       out     = (float*)d_out;

    const dim3 blk(256);

    // 1. projections
    gemm_q_kernel <<<dim3(HDIM / 64, T_SEQ / 128, N_HEADS), blk>>>(x, w_q);
    gemm_kv_kernel<<<dim3(HDIM / 64, T_SEQ / 128, 16),      blk>>>(x, w_kv);

    // 2. norms + rope
    norm_rope_q_kernel <<<(T_SEQ * N_HEADS) / 8, blk>>>(q_scale, segpos);
    norm_rope_kv_kernel<<<(T_SEQ * 16) / 8,      blk>>>(k_scale, segpos);

    // 3. attention
    static_assert(ATTN_SMEM_FLOATS * 4 < 228 * 1024, "smem too big");
    cudaFuncSetAttribute(attn_kernel, cudaFuncAttributeMaxDynamicSharedMemorySize,
                         ATTN_SMEM_FLOATS * 4);
    attn_kernel<<<dim3(T_SEQ / 64, N_HEADS), blk, ATTN_SMEM_FLOATS * 4>>>();

    // 4. output projection (single fused GEMM over all heads)
    gemm_out_kernel<<<dim3(D_MODEL / 64, T_SEQ / 128, 1), blk>>>(w_out, out);
}

// round 3
// speedup vs baseline: 1.4400x; 1.4400x over previous
#include <cuda_runtime.h>
#include <cuda_bf16.h>
#include <math.h>
#include <stdint.h>

// ---------------- problem constants ----------------
#define T_SEQ   2048
#define D_MODEL 3072
#define N_HEADS 16
#define K_HEADS 8
#define HDIM    256
#define WINDOW  1024
#define SOFT_CAP 50.0f
#define EPS 1e-6f

// ---------------- scratch (static device globals; no runtime allocs) ----------------
__device__ float g_q   [(size_t)T_SEQ * N_HEADS * HDIM];    // [t][n][h]
__device__ float g_kv  [(size_t)T_SEQ * 16 * HDIM];         // [t][c*8+kh][h]
__device__ float g_enc [(size_t)T_SEQ * N_HEADS * HDIM];    // [t][n][h]
__device__ float g_wqT [(size_t)N_HEADS * HDIM * D_MODEL];  // [n][h][d]  (K-major)
__device__ float g_wkvT[(size_t)16 * HDIM * D_MODEL];       // [c*8+kh][h][d]
__device__ float g_woutT[(size_t)D_MODEL * N_HEADS * HDIM]; // [d][nh*h]  (K-major)

// ---------------- tf32 helpers ----------------
__device__ __forceinline__ uint32_t tf32_rn(float x) {
    uint32_t u;
    asm("cvt.rna.tf32.f32 %0, %1;" : "=r"(u) : "f"(x));
    return u;
}
__device__ __forceinline__ float tf32f(float x) { return __uint_as_float(tf32_rn(x)); }

__device__ __forceinline__ void mma_tf32(float* c,
    uint32_t a0, uint32_t a1, uint32_t a2, uint32_t a3, uint32_t b0, uint32_t b1)
{
    asm volatile("mma.sync.aligned.m16n8k8.row.col.f32.tf32.tf32.f32 "
                 "{%0,%1,%2,%3},{%4,%5,%6,%7},{%8,%9},{%0,%1,%2,%3};"
                 : "+f"(c[0]), "+f"(c[1]), "+f"(c[2]), "+f"(c[3])
                 : "r"(a0), "r"(a1), "r"(a2), "r"(a3), "r"(b0), "r"(b1));
}

// ================= mma.sync tf32 GEMM =================
// CTA tile 128x128x32, 8 warps (2M x 4N), warp tile 64x32, double-buffered smem.
// A row-major [M][K]; B K-major [z][N][K]; C row-major, col offset z*czcol + n0.
// SPLIT: 3xTF32 (hi/lo) for near-fp32 accuracy.
#define LDT 36
#define GTILE (128 * LDT)

template<bool SPLIT>
__global__ __launch_bounds__(256) void gemm_mma_kernel(
    const float* __restrict__ A, const float* __restrict__ B,
    float* __restrict__ C, int Kdim, size_t b_zstride, int ldc, int czcol)
{
    extern __shared__ float smf[];
    constexpr int NBUF  = SPLIT ? 4 : 2;     // Ah,Bh[,Al,Bl]
    constexpr int STAGE = GTILE * NBUF;

    const int tid = threadIdx.x;
    const int m0  = blockIdx.x * 128;
    const int n0b = blockIdx.y * 128;
    const int z   = blockIdx.z;
    const float* Am = A + (size_t)m0 * Kdim;
    const float* Bz = B + (size_t)z * b_zstride + (size_t)n0b * Kdim;
    const int ccol = z * czcol + n0b;

    const int lr = tid >> 3;                 // 0..31 (row base for loads)
    const int lc = tid & 7;                  // 0..7  (float4 col)
    const int wid = tid >> 5, lane = tid & 31;
    const int wm = wid & 1, wn = wid >> 1;   // warp grid 2(M) x 4(N)
    const int g = lane >> 2, t = lane & 3;   // mma groupID / thread-in-group
    const int NK = Kdim / 32;

    float4 pa[4], pb[4];

    // ---- stage store (cvt + STS.128, conflict-free phases) ----
    auto store_stage = [&](float* s) {
        float* sAh = s;
        float* sBh = s + GTILE;
        float* sAl = s + 2 * GTILE;
        float* sBl = s + 3 * GTILE;
        #pragma unroll
        for (int i = 0; i < 4; i++) {
            int base = (lr + 32 * i) * LDT + lc * 4;
            float4 a = pa[i], b = pb[i];
            float4 ah = make_float4(tf32f(a.x), tf32f(a.y), tf32f(a.z), tf32f(a.w));
            float4 bh = make_float4(tf32f(b.x), tf32f(b.y), tf32f(b.z), tf32f(b.w));
            *reinterpret_cast<float4*>(&sAh[base]) = ah;
            *reinterpret_cast<float4*>(&sBh[base]) = bh;
            if (SPLIT) {
                float4 al = make_float4(tf32f(a.x - ah.x), tf32f(a.y - ah.y),
                                        tf32f(a.z - ah.z), tf32f(a.w - ah.w));
                float4 bl = make_float4(tf32f(b.x - bh.x), tf32f(b.y - bh.y),
                                        tf32f(b.z - bh.z), tf32f(b.w - bh.w));
                *reinterpret_cast<float4*>(&sAl[base]) = al;
                *reinterpret_cast<float4*>(&sBl[base]) = bl;
            }
        }
    };

    // prologue: load + store k-tile 0
    #pragma unroll
    for (int i = 0; i < 4; i++) {
        pa[i] = *reinterpret_cast<const float4*>(&Am[(size_t)(lr + 32 * i) * Kdim + lc * 4]);
        pb[i] = *reinterpret_cast<const float4*>(&Bz[(size_t)(lr + 32 * i) * Kdim + lc * 4]);
    }
    store_stage(smf);

    float acc[4][4][4];
    #pragma unroll
    for (int i = 0; i < 4; i++)
        #pragma unroll
        for (int j = 0; j < 4; j++)
            #pragma unroll
            for (int r = 0; r < 4; r++) acc[i][j][r] = 0.f;

    for (int kt = 0; kt < NK; kt++) {
        __syncthreads();
        const bool more = (kt + 1) < NK;
        if (more) {
            const int k0 = (kt + 1) * 32;
            #pragma unroll
            for (int i = 0; i < 4; i++) {
                pa[i] = *reinterpret_cast<const float4*>(&Am[(size_t)(lr + 32 * i) * Kdim + k0 + lc * 4]);
                pb[i] = *reinterpret_cast<const float4*>(&Bz[(size_t)(lr + 32 * i) * Kdim + k0 + lc * 4]);
            }
        }

        float* s   = smf + (kt & 1) * STAGE;
        float* sAh = s;
        float* sBh = s + GTILE;
        float* sAl = s + 2 * GTILE;
        float* sBl = s + 3 * GTILE;

        #pragma unroll
        for (int ks = 0; ks < 4; ks++) {
            const int c0 = ks * 8 + t;
            uint32_t ah[4][4], bh[4][2];
            uint32_t al[4][4], bl[4][2];
            #pragma unroll
            for (int i = 0; i < 4; i++) {
                const int r0 = wm * 64 + i * 16 + g;
                ah[i][0] = __float_as_uint(sAh[r0 * LDT + c0]);
                ah[i][1] = __float_as_uint(sAh[(r0 + 8) * LDT + c0]);
                ah[i][2] = __float_as_uint(sAh[r0 * LDT + c0 + 4]);
                ah[i][3] = __float_as_uint(sAh[(r0 + 8) * LDT + c0 + 4]);
                if (SPLIT) {
                    al[i][0] = __float_as_uint(sAl[r0 * LDT + c0]);
                    al[i][1] = __float_as_uint(sAl[(r0 + 8) * LDT + c0]);
                    al[i][2] = __float_as_uint(sAl[r0 * LDT + c0 + 4]);
                    al[i][3] = __float_as_uint(sAl[(r0 + 8) * LDT + c0 + 4]);
                }
            }
            #pragma unroll
            for (int j = 0; j < 4; j++) {
                const int n0 = wn * 32 + j * 8 + g;
                bh[j][0] = __float_as_uint(sBh[n0 * LDT + c0]);
                bh[j][1] = __float_as_uint(sBh[n0 * LDT + c0 + 4]);
                if (SPLIT) {
                    bl[j][0] = __float_as_uint(sBl[n0 * LDT + c0]);
                    bl[j][1] = __float_as_uint(sBl[n0 * LDT + c0 + 4]);
                }
            }
            #pragma unroll
            for (int i = 0; i < 4; i++)
                #pragma unroll
                for (int j = 0; j < 4; j++) {
                    mma_tf32(acc[i][j], ah[i][0], ah[i][1], ah[i][2], ah[i][3], bh[j][0], bh[j][1]);
                    if (SPLIT) {
                        mma_tf32(acc[i][j], ah[i][0], ah[i][1], ah[i][2], ah[i][3], bl[j][0], bl[j][1]);
                        mma_tf32(acc[i][j], al[i][0], al[i][1], al[i][2], al[i][3], bh[j][0], bh[j][1]);
                    }
                }
        }
        if (more) store_stage(smf + ((kt + 1) & 1) * STAGE);
    }

    // epilogue
    #pragma unroll
    for (int i = 0; i < 4; i++) {
        const int r0 = m0 + wm * 64 + i * 16 + g;
        #pragma unroll
        for (int j = 0; j < 4; j++) {
            const int c0 = ccol + wn * 32 + j * 8 + t * 2;
            *reinterpret_cast<float2*>(&C[(size_t)r0 * ldc + c0]) =
                make_float2(acc[i][j][0], acc[i][j][1]);
            *reinterpret_cast<float2*>(&C[(size_t)(r0 + 8) * ldc + c0]) =
                make_float2(acc[i][j][2], acc[i][j][3]);
        }
    }
}

#define GEMM_SMEM_SPLIT (2 * 4 * GTILE * 4)   // 147456 B
#define GEMM_SMEM_PLAIN (2 * 2 * GTILE * 4)   // 73728 B

// ================= weight transpose: in [z][R][C] -> out [z][C][R] =================
__global__ __launch_bounds__(256) void transpose_kernel(const float* __restrict__ in,
                                                        float* __restrict__ out, int R, int C)
{
    __shared__ float t[32][33];
    size_t zo = (size_t)blockIdx.z * R * C;
    int c0 = blockIdx.x * 32, r0 = blockIdx.y * 32;
    int tx = threadIdx.x & 31, ty = threadIdx.x >> 5;   // 32 x 8
    #pragma unroll
    for (int i = 0; i < 32; i += 8)
        t[ty + i][tx] = in[zo + (size_t)(r0 + ty + i) * C + c0 + tx];
    __syncthreads();
    #pragma unroll
    for (int i = 0; i < 32; i += 8)
        out[zo + (size_t)(c0 + ty + i) * R + r0 + tx] = t[tx][ty + i];
}

// ================= RMS-norm (+scale) (+RoPE) =================
__device__ __forceinline__ void rope_apply(float v[8], int lane, int pos)
{
    #pragma unroll
    for (int j = 0; j < 4; j++) {
        int hh = lane + 32 * j;
        float ts = powf(10000.0f, (float)hh * (1.0f / 128.0f));
        float arg = (float)pos / ts;
        float sn, cs;
        sincosf(arg, &sn, &cs);
        float f = v[j], s = v[j + 4];
        v[j]     = f * cs - s * sn;
        v[j + 4] = s * cs + f * sn;
    }
}

__global__ __launch_bounds__(256) void norm_rope_q_kernel(const float* __restrict__ qscale,
                                                          const int* __restrict__ segpos)
{
    int row  = blockIdx.x * 8 + (threadIdx.x >> 5);
    int lane = threadIdx.x & 31;
    int t = row >> 4;
    float* p = g_q + (size_t)row * HDIM;

    float v[8]; float ss = 0.f;
    #pragma unroll
    for (int j = 0; j < 8; j++) { v[j] = p[lane + 32 * j]; ss += v[j] * v[j]; }
    #pragma unroll
    for (int o = 16; o > 0; o >>= 1) ss += __shfl_xor_sync(0xffffffffu, ss, o);
    float rstd = rsqrtf(ss * (1.0f / 256.0f) + EPS);

    #pragma unroll
    for (int j = 0; j < 8; j++) {
        int h = lane + 32 * j;
        v[j] = v[j] * rstd * (1.0f + qscale[h]);
    }
    rope_apply(v, lane, segpos[t]);
    #pragma unroll
    for (int j = 0; j < 8; j++) p[lane + 32 * j] = v[j];
}

__global__ __launch_bounds__(256) void norm_rope_kv_kernel(const float* __restrict__ kscale,
                                                           const int* __restrict__ segpos)
{
    int row  = blockIdx.x * 8 + (threadIdx.x >> 5);
    int lane = threadIdx.x & 31;
    int t    = row >> 4;
    int head = row & 15;
    float* p = g_kv + (size_t)row * HDIM;

    float v[8]; float ss = 0.f;
    #pragma unroll
    for (int j = 0; j < 8; j++) { v[j] = p[lane + 32 * j]; ss += v[j] * v[j]; }
    #pragma unroll
    for (int o = 16; o > 0; o >>= 1) ss += __shfl_xor_sync(0xffffffffu, ss, o);
    float rstd = rsqrtf(ss * (1.0f / 256.0f) + EPS);

    if (head < 8) {
        #pragma unroll
        for (int j = 0; j < 8; j++) {
            int h = lane + 32 * j;
            v[j] = v[j] * rstd * (1.0f + kscale[h]);
        }
        rope_apply(v, lane, segpos[t]);
    } else {
        #pragma unroll
        for (int j = 0; j < 8; j++) v[j] *= rstd;
    }
    #pragma unroll
    for (int j = 0; j < 8; j++) p[lane + 32 * j] = v[j];
}

// ================= flash attention (SIMT fp32) =================
#define ATTN_SMEM_FLOATS (64 * 256 + 32 * 260 + 32 * 260 + 64 * 32)

__global__ __launch_bounds__(256, 1) void attn_kernel()
{
    extern __shared__ float sm[];
    float* qs = sm;
    float* ks = sm + 64 * 256;
    float* vs = ks + 32 * 260;
    float* ps = vs + 32 * 260;

    const int tile = blockIdx.x;
    const int n    = blockIdx.y;
    const int kh   = n >> 1;
    const int t0   = tile * 64;
    const int tid  = threadIdx.x;
    const int rg   = tid >> 4;
    const int cg   = tid & 15;
    const int r0   = rg << 2;

    #pragma unroll
    for (int l = 0; l < 16; l++) {
        int idx = tid + l * 256;
        int r = idx >> 6;
        int c = (idx & 63) << 2;
        *reinterpret_cast<float4*>(&qs[r * 256 + c]) =
            *reinterpret_cast<const float4*>(&g_q[((size_t)(t0 + r) * 16 + n) * 256 + c]);
    }

    float4 o[4][4];
    #pragma unroll
    for (int i = 0; i < 4; i++)
        #pragma unroll
        for (int j = 0; j < 4; j++) o[i][j] = make_float4(0.f, 0.f, 0.f, 0.f);
    float mrow[4], lrow[4];
    #pragma unroll
    for (int i = 0; i < 4; i++) { mrow[i] = -1e30f; lrow[i] = 0.f; }

    int s_lo = t0 - (WINDOW - 1); if (s_lo < 0) s_lo = 0; s_lo &= ~31;
    const int s_hi = t0 + 63;

    __syncthreads();

    for (int sc0 = s_lo; sc0 <= s_hi; sc0 += 32) {
        #pragma unroll
        for (int l = 0; l < 8; l++) {
            int idx = tid + l * 256;
            int r = idx >> 6;
            int c = (idx & 63) << 2;
            *reinterpret_cast<float4*>(&ks[r * 260 + c]) =
                *reinterpret_cast<const float4*>(&g_kv[((size_t)(sc0 + r) * 16 + kh) * 256 + c]);
            *reinterpret_cast<float4*>(&vs[r * 260 + c]) =
                *reinterpret_cast<const float4*>(&g_kv[((size_t)(sc0 + r) * 16 + 8 + kh) * 256 + c]);
        }
        __syncthreads();

        float s[4][2];
        #pragma unroll
        for (int i = 0; i < 4; i++) { s[i][0] = 0.f; s[i][1] = 0.f; }

        #pragma unroll 4
        for (int k = 0; k < 256; k += 4) {
            float4 b0 = *reinterpret_cast<const float4*>(&ks[cg * 260 + k]);
            float4 b1 = *reinterpret_cast<const float4*>(&ks[(cg + 16) * 260 + k]);
            #pragma unroll
            for (int i = 0; i < 4; i++) {
                float4 a = *reinterpret_cast<const float4*>(&qs[(r0 + i) * 256 + k]);
                s[i][0] += a.x * b0.x + a.y * b0.y + a.z * b0.z + a.w * b0.w;
                s[i][1] += a.x * b1.x + a.y * b1.y + a.z * b1.z + a.w * b1.w;
            }
        }

        #pragma unroll
        for (int i = 0; i < 4; i++) {
            int tq = t0 + r0 + i;
            #pragma unroll
            for (int j = 0; j < 2; j++) {
                int sk = sc0 + cg + 16 * j;
                float val = tanhf(s[i][j] * (1.0f / SOFT_CAP)) * SOFT_CAP;
                bool ok = (sk <= tq) && (sk > tq - WINDOW);
                s[i][j] = ok ? val : -1e30f;
            }
        }

        #pragma unroll
        for (int i = 0; i < 4; i++) {
            float mx = fmaxf(s[i][0], s[i][1]);
            #pragma unroll
            for (int off = 8; off > 0; off >>= 1)
                mx = fmaxf(mx, __shfl_xor_sync(0xffffffffu, mx, off));
            float m_new = fmaxf(mrow[i], mx);
            float alpha = __expf(mrow[i] - m_new);
            float p0 = __expf(s[i][0] - m_new);
            float p1 = __expf(s[i][1] - m_new);
            float rs = p0 + p1;
            #pragma unroll
            for (int off = 8; off > 0; off >>= 1)
                rs += __shfl_xor_sync(0xffffffffu, rs, off);
            lrow[i] = lrow[i] * alpha + rs;
            mrow[i] = m_new;
            #pragma unroll
            for (int jj = 0; jj < 4; jj++) {
                o[i][jj].x *= alpha; o[i][jj].y *= alpha;
                o[i][jj].z *= alpha; o[i][jj].w *= alpha;
            }
            ps[(r0 + i) * 32 + cg]      = p0;
            ps[(r0 + i) * 32 + cg + 16] = p1;
        }
        __syncthreads();

        #pragma unroll 4
        for (int sk = 0; sk < 32; sk++) {
            float p[4];
            #pragma unroll
            for (int i = 0; i < 4; i++) p[i] = ps[(r0 + i) * 32 + sk];
            #pragma unroll
            for (int jj = 0; jj < 4; jj++) {
                float4 v = *reinterpret_cast<const float4*>(&vs[sk * 260 + cg * 4 + jj * 64]);
                #pragma unroll
                for (int i = 0; i < 4; i++) {
                    o[i][jj].x = fmaf(p[i], v.x, o[i][jj].x);
                    o[i][jj].y = fmaf(p[i], v.y, o[i][jj].y);
                    o[i][jj].z = fmaf(p[i], v.z, o[i][jj].z);
                    o[i][jj].w = fmaf(p[i], v.w, o[i][jj].w);
                }
            }
        }
        __syncthreads();
    }

    #pragma unroll
    for (int i = 0; i < 4; i++) {
        float inv = 1.0f / lrow[i];
        int t = t0 + r0 + i;
        #pragma unroll
        for (int jj = 0; jj < 4; jj++) {
            float4 v = o[i][jj];
            v.x *= inv; v.y *= inv; v.z *= inv; v.w *= inv;
            *reinterpret_cast<float4*>(&g_enc[((size_t)t * 16 + n) * 256 + cg * 4 + jj * 64]) = v;
        }
    }
}

// ================= launch =================
extern "C" void kernel_launch(void* const* d_in, const int* in_sizes, int n_in,
                              void* d_out, int out_size)
{
    const float* x       = (const float*)d_in[0];
    const int*   segpos  = (const int*)  d_in[1];
    const float* w_q     = (const float*)d_in[3];
    const float* w_kv    = (const float*)d_in[4];
    const float* w_out   = (const float*)d_in[5];
    const float* q_scale = (const float*)d_in[6];
    const float* k_scale = (const float*)d_in[7];
    float*       out     = (float*)d_out;

    float *wqT, *wkvT, *woutT, *gq, *gkv, *genc;
    cudaGetSymbolAddress((void**)&wqT,   g_wqT);
    cudaGetSymbolAddress((void**)&wkvT,  g_wkvT);
    cudaGetSymbolAddress((void**)&woutT, g_woutT);
    cudaGetSymbolAddress((void**)&gq,    g_q);
    cudaGetSymbolAddress((void**)&gkv,   g_kv);
    cudaGetSymbolAddress((void**)&genc,  g_enc);

    const dim3 blk(256);

    // 0. weight transposes to K-major [N][K]
    transpose_kernel<<<dim3(HDIM / 32, D_MODEL / 32, 16), blk>>>(w_q,  wqT,  D_MODEL, HDIM);
    transpose_kernel<<<dim3(HDIM / 32, D_MODEL / 32, 16), blk>>>(w_kv, wkvT, D_MODEL, HDIM);
    transpose_kernel<<<dim3(D_MODEL / 32, (N_HEADS * HDIM) / 32, 1), blk>>>(w_out, woutT, N_HEADS * HDIM, D_MODEL);

    // 1. projections (mma.sync tf32; Q/KV use 3xTF32 split)
    cudaFuncSetAttribute(gemm_mma_kernel<true>,  cudaFuncAttributeMaxDynamicSharedMemorySize, GEMM_SMEM_SPLIT);
    cudaFuncSetAttribute(gemm_mma_kernel<false>, cudaFuncAttributeMaxDynamicSharedMemorySize, GEMM_SMEM_PLAIN);

    gemm_mma_kernel<true><<<dim3(T_SEQ / 128, HDIM / 128, 16), blk, GEMM_SMEM_SPLIT>>>(
        x, wqT, gq, D_MODEL, (size_t)HDIM * D_MODEL, N_HEADS * HDIM, HDIM);
    gemm_mma_kernel<true><<<dim3(T_SEQ / 128, HDIM / 128, 16), blk, GEMM_SMEM_SPLIT>>>(
        x, wkvT, gkv, D_MODEL, (size_t)HDIM * D_MODEL, 16 * HDIM, HDIM);

    // 2. norms + rope
    norm_rope_q_kernel <<<(T_SEQ * N_HEADS) / 8, blk>>>(q_scale, segpos);
    norm_rope_kv_kernel<<<(T_SEQ * 16) / 8,      blk>>>(k_scale, segpos);

    // 3. attention
    cudaFuncSetAttribute(attn_kernel, cudaFuncAttributeMaxDynamicSharedMemorySize,
                         ATTN_SMEM_FLOATS * 4);
    attn_kernel<<<dim3(T_SEQ / 64, N_HEADS), blk, ATTN_SMEM_FLOATS * 4>>>();

    // 4. output projection (single-pass tf32)
    gemm_mma_kernel<false><<<dim3(T_SEQ / 128, D_MODEL / 128, 1), blk, GEMM_SMEM_PLAIN>>>(
        genc, woutT, out, N_HEADS * HDIM, 0, D_MODEL, 0);
}

// round 4
// speedup vs baseline: 1.7336x; 1.2039x over previous
#include <cuda_runtime.h>
#include <cuda_bf16.h>
#include <math.h>
#include <stdint.h>

// ---------------- problem constants ----------------
#define T_SEQ   2048
#define D_MODEL 3072
#define N_HEADS 16
#define K_HEADS 8
#define HDIM    256
#define WINDOW  1024
#define SOFT_CAP 50.0f
#define EPS 1e-6f

// ---------------- scratch (static device globals) ----------------
__device__ float g_q  [(size_t)T_SEQ * N_HEADS * HDIM];
__device__ float g_kv [(size_t)T_SEQ * 16 * HDIM];
__device__ __nv_bfloat16 g_xh [(size_t)T_SEQ * D_MODEL];
__device__ __nv_bfloat16 g_xl [(size_t)T_SEQ * D_MODEL];
__device__ __nv_bfloat16 g_wqh [(size_t)N_HEADS * HDIM * D_MODEL];
__device__ __nv_bfloat16 g_wql [(size_t)N_HEADS * HDIM * D_MODEL];
__device__ __nv_bfloat16 g_wkvh[(size_t)16 * HDIM * D_MODEL];
__device__ __nv_bfloat16 g_wkvl[(size_t)16 * HDIM * D_MODEL];
__device__ __nv_bfloat16 g_woh [(size_t)D_MODEL * N_HEADS * HDIM];
__device__ __nv_bfloat16 g_wol [(size_t)D_MODEL * N_HEADS * HDIM];
__device__ __nv_bfloat16 g_ench[(size_t)T_SEQ * N_HEADS * HDIM];
__device__ __nv_bfloat16 g_encl[(size_t)T_SEQ * N_HEADS * HDIM];

// ---------------- low-level helpers ----------------
__device__ __forceinline__ uint32_t smem_u32(const void* p) {
    uint32_t a;
    asm("{ .reg .u64 t; cvta.to.shared.u64 t, %1; cvt.u32.u64 %0, t; }" : "=r"(a) : "l"(p));
    return a;
}
__device__ __forceinline__ void cp_async16(uint32_t dst, const void* src) {
    asm volatile("cp.async.cg.shared.global [%0], [%1], 16;" :: "r"(dst), "l"(src));
}
__device__ __forceinline__ void cp_commit() { asm volatile("cp.async.commit_group;"); }
__device__ __forceinline__ void cp_wait1()  { asm volatile("cp.async.wait_group 1;"); }

__device__ __forceinline__ void ldsm_x4(uint32_t& r0, uint32_t& r1, uint32_t& r2, uint32_t& r3,
                                        uint32_t addr) {
    asm volatile("ldmatrix.sync.aligned.m8n8.x4.shared.b16 {%0,%1,%2,%3}, [%4];"
                 : "=r"(r0), "=r"(r1), "=r"(r2), "=r"(r3) : "r"(addr));
}
__device__ __forceinline__ void mma_bf16(float* c, const uint32_t* a, const uint32_t* b) {
    asm volatile("mma.sync.aligned.m16n8k16.row.col.f32.bf16.bf16.f32 "
                 "{%0,%1,%2,%3},{%4,%5,%6,%7},{%8,%9},{%0,%1,%2,%3};"
                 : "+f"(c[0]), "+f"(c[1]), "+f"(c[2]), "+f"(c[3])
                 : "r"(a[0]), "r"(a[1]), "r"(a[2]), "r"(a[3]), "r"(b[0]), "r"(b[1]));
}
__device__ __forceinline__ void split_bf16(float x, __nv_bfloat16& h, __nv_bfloat16& l) {
    h = __float2bfloat16(x);
    l = __float2bfloat16(x - __bfloat162float(h));
}

// ================= split-bf16 GEMM (3-term compensated) =================
// CTA tile 128x128x32, 8 warps (2M x 4N), 3-stage cp.async pipeline, ldmatrix frags.
// A planes [M][K], B planes [z][N][K] (K-major), C fp32 row-major.
#define LDH 40                 // halves per smem row (80 B, conflict-free & 16B-aligned)
#define PLANE_B (128 * LDH * 2)  // 10240 B per plane
#define STAGE_B (4 * PLANE_B)    // Ah, Al, Bh, Bl = 40960 B
#define NSTAGE 3
#define GEMM_SMEM (NSTAGE * STAGE_B)

__global__ __launch_bounds__(256) void gemm_bf16_kernel(
    const __nv_bfloat16* __restrict__ Ah, const __nv_bfloat16* __restrict__ Al,
    const __nv_bfloat16* __restrict__ Bh, const __nv_bfloat16* __restrict__ Bl,
    float* __restrict__ C, int Kdim, size_t b_zstride, int ldc, int czcol)
{
    extern __shared__ char smem[];
    const uint32_t sbase = smem_u32(smem);
    const int tid = threadIdx.x;
    const int m0 = blockIdx.x * 128, n0b = blockIdx.y * 128, z = blockIdx.z;
    const __nv_bfloat16* Ahm = Ah + (size_t)m0 * Kdim;
    const __nv_bfloat16* Alm = Al + (size_t)m0 * Kdim;
    const __nv_bfloat16* Bhz = Bh + (size_t)z * b_zstride + (size_t)n0b * Kdim;
    const __nv_bfloat16* Blz = Bl + (size_t)z * b_zstride + (size_t)n0b * Kdim;
    const int ccol = z * czcol + n0b;
    const int NK = Kdim / 32;

    const int wid = tid >> 5, lane = tid & 31;
    const int wm = wid & 1, wn = wid >> 1;
    const int g = lane >> 2, t4 = lane & 3;

    // producer chunk coords: 512 16B-chunks per plane, 2 per thread
    const int pr0 = tid >> 2, pc0 = tid & 3;           // chunk 0: row tid/4? -> use idx scheme
    // (idx = tid + i*256; r = idx>>2; c = idx&3)

    auto issue_stage = [&](int s, int kt) {
        const int k0 = kt * 32;
        #pragma unroll
        for (int i = 0; i < 2; i++) {
            int idx = tid + i * 256;
            int r = idx >> 2, c = idx & 3;
            size_t goff = (size_t)r * Kdim + k0 + c * 8;
            uint32_t d = sbase + s * STAGE_B + r * (LDH * 2) + c * 16;
            cp_async16(d,               Ahm + goff);
            cp_async16(d + PLANE_B,     Alm + goff);
            cp_async16(d + 2 * PLANE_B, Bhz + goff);
            cp_async16(d + 3 * PLANE_B, Blz + goff);
        }
    };

    float acc[4][4][4];
    #pragma unroll
    for (int i = 0; i < 4; i++)
        #pragma unroll
        for (int j = 0; j < 4; j++)
            #pragma unroll
            for (int r = 0; r < 4; r++) acc[i][j][r] = 0.f;

    // lane-derived ldmatrix offsets
    const int arow = wm * 64 + (lane & 7) + ((lane >> 3) & 1) * 8;  // + i*16
    const int akof = ((lane >> 4) & 1) * 8;                          // + ks*16
    const int brow = wn * 32 + (lane & 7) + ((lane >> 4) & 1) * 8;   // + jp*16
    const int bkof = ((lane >> 3) & 1) * 8;                          // + ks*16

    issue_stage(0, 0); cp_commit();
    issue_stage(1, 1); cp_commit();

    for (int kt = 0; kt < NK; kt++) {
        cp_wait1();
        __syncthreads();
        if (kt + 2 < NK) issue_stage((kt + 2) % NSTAGE, kt + 2);
        cp_commit();

        const uint32_t st = sbase + (kt % NSTAGE) * STAGE_B;
        #pragma unroll
        for (int ks = 0; ks < 2; ks++) {
            uint32_t ah[4][4], al[4][4], bh[4][2], bl[4][2];
            #pragma unroll
            for (int i = 0; i < 4; i++) {
                uint32_t ad = st + (arow + i * 16) * (LDH * 2) + (ks * 16 + akof) * 2;
                ldsm_x4(ah[i][0], ah[i][1], ah[i][2], ah[i][3], ad);
                ldsm_x4(al[i][0], al[i][1], al[i][2], al[i][3], ad + PLANE_B);
            }
            #pragma unroll
            for (int jp = 0; jp < 2; jp++) {
                uint32_t bd = st + 2 * PLANE_B + (brow + jp * 16) * (LDH * 2) + (ks * 16 + bkof) * 2;
                uint32_t r0, r1, r2, r3;
                ldsm_x4(r0, r1, r2, r3, bd);
                bh[2 * jp][0] = r0; bh[2 * jp][1] = r1;
                bh[2 * jp + 1][0] = r2; bh[2 * jp + 1][1] = r3;
                ldsm_x4(r0, r1, r2, r3, bd + PLANE_B);
                bl[2 * jp][0] = r0; bl[2 * jp][1] = r1;
                bl[2 * jp + 1][0] = r2; bl[2 * jp + 1][1] = r3;
            }
            #pragma unroll
            for (int i = 0; i < 4; i++)
                #pragma unroll
                for (int j = 0; j < 4; j++) {
                    mma_bf16(acc[i][j], ah[i], bh[j]);
                    mma_bf16(acc[i][j], ah[i], bl[j]);
                    mma_bf16(acc[i][j], al[i], bh[j]);
                }
        }
    }

    // epilogue (same fragment->C mapping as before)
    #pragma unroll
    for (int i = 0; i < 4; i++) {
        const int r0 = m0 + wm * 64 + i * 16 + g;
        #pragma unroll
        for (int j = 0; j < 4; j++) {
            const int c0 = ccol + wn * 32 + j * 8 + t4 * 2;
            *reinterpret_cast<float2*>(&C[(size_t)r0 * ldc + c0]) =
                make_float2(acc[i][j][0], acc[i][j][1]);
            *reinterpret_cast<float2*>(&C[(size_t)(r0 + 8) * ldc + c0]) =
                make_float2(acc[i][j][2], acc[i][j][3]);
        }
    }
}

// ================= x -> bf16 hi/lo planes =================
__global__ __launch_bounds__(256) void convert_x_kernel(const float* __restrict__ x)
{
    size_t i = ((size_t)blockIdx.x * 256 + threadIdx.x) * 4;
    float4 v = *reinterpret_cast<const float4*>(x + i);
    __nv_bfloat16 h[4], l[4];
    split_bf16(v.x, h[0], l[0]); split_bf16(v.y, h[1], l[1]);
    split_bf16(v.z, h[2], l[2]); split_bf16(v.w, h[3], l[3]);
    *reinterpret_cast<__nv_bfloat162*>(g_xh + i)     = __nv_bfloat162(h[0], h[1]);
    *reinterpret_cast<__nv_bfloat162*>(g_xh + i + 2) = __nv_bfloat162(h[2], h[3]);
    *reinterpret_cast<__nv_bfloat162*>(g_xl + i)     = __nv_bfloat162(l[0], l[1]);
    *reinterpret_cast<__nv_bfloat162*>(g_xl + i + 2) = __nv_bfloat162(l[2], l[3]);
}

// ================= transpose + convert: [z][R][C] fp32 -> [z][C][R] bf16 hi/lo =================
__global__ __launch_bounds__(256) void transpose_conv_kernel(
    const float* __restrict__ in, __nv_bfloat16* __restrict__ outh,
    __nv_bfloat16* __restrict__ outl, int R, int C)
{
    __shared__ float t[32][33];
    size_t zo = (size_t)blockIdx.z * R * C;
    int c0 = blockIdx.x * 32, r0 = blockIdx.y * 32;
    int tx = threadIdx.x & 31, ty = threadIdx.x >> 5;
    #pragma unroll
    for (int i = 0; i < 32; i += 8)
        t[ty + i][tx] = in[zo + (size_t)(r0 + ty + i) * C + c0 + tx];
    __syncthreads();
    #pragma unroll
    for (int i = 0; i < 32; i += 8) {
        float v = t[tx][ty + i];
        __nv_bfloat16 h, l;
        split_bf16(v, h, l);
        size_t o = zo + (size_t)(c0 + ty + i) * R + r0 + tx;
        outh[o] = h;
        outl[o] = l;
    }
}

// ================= RMS-norm (+scale) (+RoPE) =================
__device__ __forceinline__ void rope_apply(float v[8], int lane, int pos)
{
    #pragma unroll
    for (int j = 0; j < 4; j++) {
        int hh = lane + 32 * j;
        float ts = powf(10000.0f, (float)hh * (1.0f / 128.0f));
        float arg = (float)pos / ts;
        float sn, cs;
        sincosf(arg, &sn, &cs);
        float f = v[j], s = v[j + 4];
        v[j]     = f * cs - s * sn;
        v[j + 4] = s * cs + f * sn;
    }
}

__global__ __launch_bounds__(256) void norm_rope_q_kernel(const float* __restrict__ qscale,
                                                          const int* __restrict__ segpos)
{
    int row  = blockIdx.x * 8 + (threadIdx.x >> 5);
    int lane = threadIdx.x & 31;
    int t = row >> 4;
    float* p = g_q + (size_t)row * HDIM;

    float v[8]; float ss = 0.f;
    #pragma unroll
    for (int j = 0; j < 8; j++) { v[j] = p[lane + 32 * j]; ss += v[j] * v[j]; }
    #pragma unroll
    for (int o = 16; o > 0; o >>= 1) ss += __shfl_xor_sync(0xffffffffu, ss, o);
    float rstd = rsqrtf(ss * (1.0f / 256.0f) + EPS);

    #pragma unroll
    for (int j = 0; j < 8; j++) {
        int h = lane + 32 * j;
        v[j] = v[j] * rstd * (1.0f + qscale[h]);
    }
    rope_apply(v, lane, segpos[t]);
    #pragma unroll
    for (int j = 0; j < 8; j++) p[lane + 32 * j] = v[j];
}

__global__ __launch_bounds__(256) void norm_rope_kv_kernel(const float* __restrict__ kscale,
                                                           const int* __restrict__ segpos)
{
    int row  = blockIdx.x * 8 + (threadIdx.x >> 5);
    int lane = threadIdx.x & 31;
    int t    = row >> 4;
    int head = row & 15;
    float* p = g_kv + (size_t)row * HDIM;

    float v[8]; float ss = 0.f;
    #pragma unroll
    for (int j = 0; j < 8; j++) { v[j] = p[lane + 32 * j]; ss += v[j] * v[j]; }
    #pragma unroll
    for (int o = 16; o > 0; o >>= 1) ss += __shfl_xor_sync(0xffffffffu, ss, o);
    float rstd = rsqrtf(ss * (1.0f / 256.0f) + EPS);

    if (head < 8) {
        #pragma unroll
        for (int j = 0; j < 8; j++) {
            int h = lane + 32 * j;
            v[j] = v[j] * rstd * (1.0f + kscale[h]);
        }
        rope_apply(v, lane, segpos[t]);
    } else {
        #pragma unroll
        for (int j = 0; j < 8; j++) v[j] *= rstd;
    }
    #pragma unroll
    for (int j = 0; j < 8; j++) p[lane + 32 * j] = v[j];
}

// ================= flash attention (SIMT fp32); epilogue writes bf16 hi/lo enc =================
#define ATTN_SMEM_FLOATS (64 * 256 + 32 * 260 + 32 * 260 + 64 * 32)

__global__ __launch_bounds__(256, 1) void attn_kernel()
{
    extern __shared__ float sm[];
    float* qs = sm;
    float* ks = sm + 64 * 256;
    float* vs = ks + 32 * 260;
    float* ps = vs + 32 * 260;

    const int tile = blockIdx.x;
    const int n    = blockIdx.y;
    const int kh   = n >> 1;
    const int t0   = tile * 64;
    const int tid  = threadIdx.x;
    const int rg   = tid >> 4;
    const int cg   = tid & 15;
    const int r0   = rg << 2;

    #pragma unroll
    for (int l = 0; l < 16; l++) {
        int idx = tid + l * 256;
        int r = idx >> 6;
        int c = (idx & 63) << 2;
        *reinterpret_cast<float4*>(&qs[r * 256 + c]) =
            *reinterpret_cast<const float4*>(&g_q[((size_t)(t0 + r) * 16 + n) * 256 + c]);
    }

    float4 o[4][4];
    #pragma unroll
    for (int i = 0; i < 4; i++)
        #pragma unroll
        for (int j = 0; j < 4; j++) o[i][j] = make_float4(0.f, 0.f, 0.f, 0.f);
    float mrow[4], lrow[4];
    #pragma unroll
    for (int i = 0; i < 4; i++) { mrow[i] = -1e30f; lrow[i] = 0.f; }

    int s_lo = t0 - (WINDOW - 1); if (s_lo < 0) s_lo = 0; s_lo &= ~31;
    const int s_hi = t0 + 63;

    __syncthreads();

    for (int sc0 = s_lo; sc0 <= s_hi; sc0 += 32) {
        #pragma unroll
        for (int l = 0; l < 8; l++) {
            int idx = tid + l * 256;
            int r = idx >> 6;
            int c = (idx & 63) << 2;
            *reinterpret_cast<float4*>(&ks[r * 260 + c]) =
                *reinterpret_cast<const float4*>(&g_kv[((size_t)(sc0 + r) * 16 + kh) * 256 + c]);
            *reinterpret_cast<float4*>(&vs[r * 260 + c]) =
                *reinterpret_cast<const float4*>(&g_kv[((size_t)(sc0 + r) * 16 + 8 + kh) * 256 + c]);
        }
        __syncthreads();

        float s[4][2];
        #pragma unroll
        for (int i = 0; i < 4; i++) { s[i][0] = 0.f; s[i][1] = 0.f; }

        #pragma unroll 4
        for (int k = 0; k < 256; k += 4) {
            float4 b0 = *reinterpret_cast<const float4*>(&ks[cg * 260 + k]);
            float4 b1 = *reinterpret_cast<const float4*>(&ks[(cg + 16) * 260 + k]);
            #pragma unroll
            for (int i = 0; i < 4; i++) {
                float4 a = *reinterpret_cast<const float4*>(&qs[(r0 + i) * 256 + k]);
                s[i][0] += a.x * b0.x + a.y * b0.y + a.z * b0.z + a.w * b0.w;
                s[i][1] += a.x * b1.x + a.y * b1.y + a.z * b1.z + a.w * b1.w;
            }
        }

        #pragma unroll
        for (int i = 0; i < 4; i++) {
            int tq = t0 + r0 + i;
            #pragma unroll
            for (int j = 0; j < 2; j++) {
                int sk = sc0 + cg + 16 * j;
                float val = tanhf(s[i][j] * (1.0f / SOFT_CAP)) * SOFT_CAP;
                bool ok = (sk <= tq) && (sk > tq - WINDOW);
                s[i][j] = ok ? val : -1e30f;
            }
        }

        #pragma unroll
        for (int i = 0; i < 4; i++) {
            float mx = fmaxf(s[i][0], s[i][1]);
            #pragma unroll
            for (int off = 8; off > 0; off >>= 1)
                mx = fmaxf(mx, __shfl_xor_sync(0xffffffffu, mx, off));
            float m_new = fmaxf(mrow[i], mx);
            float alpha = __expf(mrow[i] - m_new);
            float p0 = __expf(s[i][0] - m_new);
            float p1 = __expf(s[i][1] - m_new);
            float rs = p0 + p1;
            #pragma unroll
            for (int off = 8; off > 0; off >>= 1)
                rs += __shfl_xor_sync(0xffffffffu, rs, off);
            lrow[i] = lrow[i] * alpha + rs;
            mrow[i] = m_new;
            #pragma unroll
            for (int jj = 0; jj < 4; jj++) {
                o[i][jj].x *= alpha; o[i][jj].y *= alpha;
                o[i][jj].z *= alpha; o[i][jj].w *= alpha;
            }
            ps[(r0 + i) * 32 + cg]      = p0;
            ps[(r0 + i) * 32 + cg + 16] = p1;
        }
        __syncthreads();

        #pragma unroll 4
        for (int sk = 0; sk < 32; sk++) {
            float p[4];
            #pragma unroll
            for (int i = 0; i < 4; i++) p[i] = ps[(r0 + i) * 32 + sk];
            #pragma unroll
            for (int jj = 0; jj < 4; jj++) {
                float4 v = *reinterpret_cast<const float4*>(&vs[sk * 260 + cg * 4 + jj * 64]);
                #pragma unroll
                for (int i = 0; i < 4; i++) {
                    o[i][jj].x = fmaf(p[i], v.x, o[i][jj].x);
                    o[i][jj].y = fmaf(p[i], v.y, o[i][jj].y);
                    o[i][jj].z = fmaf(p[i], v.z, o[i][jj].z);
                    o[i][jj].w = fmaf(p[i], v.w, o[i][jj].w);
                }
            }
        }
        __syncthreads();
    }

    // normalize, split to bf16 hi/lo planes for the out-projection
    #pragma unroll
    for (int i = 0; i < 4; i++) {
        float inv = 1.0f / lrow[i];
        int t = t0 + r0 + i;
        #pragma unroll
        for (int jj = 0; jj < 4; jj++) {
            float4 v = o[i][jj];
            v.x *= inv; v.y *= inv; v.z *= inv; v.w *= inv;
            size_t base = ((size_t)t * 16 + n) * 256 + cg * 4 + jj * 64;
            __nv_bfloat16 h0, l0, h1, l1, h2, l2, h3, l3;
            split_bf16(v.x, h0, l0); split_bf16(v.y, h1, l1);
            split_bf16(v.z, h2, l2); split_bf16(v.w, h3, l3);
            *reinterpret_cast<__nv_bfloat162*>(g_ench + base)     = __nv_bfloat162(h0, h1);
            *reinterpret_cast<__nv_bfloat162*>(g_ench + base + 2) = __nv_bfloat162(h2, h3);
            *reinterpret_cast<__nv_bfloat162*>(g_encl + base)     = __nv_bfloat162(l0, l1);
            *reinterpret_cast<__nv_bfloat162*>(g_encl + base + 2) = __nv_bfloat162(l2, l3);
        }
    }
}

// ================= launch =================
extern "C" void kernel_launch(void* const* d_in, const int* in_sizes, int n_in,
                              void* d_out, int out_size)
{
    const float* x       = (const float*)d_in[0];
    const int*   segpos  = (const int*)  d_in[1];
    const float* w_q     = (const float*)d_in[3];
    const float* w_kv    = (const float*)d_in[4];
    const float* w_out   = (const float*)d_in[5];
    const float* q_scale = (const float*)d_in[6];
    const float* k_scale = (const float*)d_in[7];
    float*       out     = (float*)d_out;

    __nv_bfloat16 *xh, *xl, *wqh, *wql, *wkvh, *wkvl, *woh, *wol, *ench, *encl;
    float *gq, *gkv;
    cudaGetSymbolAddress((void**)&xh,   g_xh);
    cudaGetSymbolAddress((void**)&xl,   g_xl);
    cudaGetSymbolAddress((void**)&wqh,  g_wqh);
    cudaGetSymbolAddress((void**)&wql,  g_wql);
    cudaGetSymbolAddress((void**)&wkvh, g_wkvh);
    cudaGetSymbolAddress((void**)&wkvl, g_wkvl);
    cudaGetSymbolAddress((void**)&woh,  g_woh);
    cudaGetSymbolAddress((void**)&wol,  g_wol);
    cudaGetSymbolAddress((void**)&ench, g_ench);
    cudaGetSymbolAddress((void**)&encl, g_encl);
    cudaGetSymbolAddress((void**)&gq,   g_q);
    cudaGetSymbolAddress((void**)&gkv,  g_kv);

    const dim3 blk(256);

    // 0. precision prep: x planes + transposed/converted weights
    convert_x_kernel<<<(T_SEQ * D_MODEL) / (256 * 4), blk>>>(x);
    transpose_conv_kernel<<<dim3(HDIM / 32, D_MODEL / 32, 16), blk>>>(w_q,  wqh, wql, D_MODEL, HDIM);
    transpose_conv_kernel<<<dim3(HDIM / 32, D_MODEL / 32, 16), blk>>>(w_kv, wkvh, wkvl, D_MODEL, HDIM);
    transpose_conv_kernel<<<dim3(D_MODEL / 32, (N_HEADS * HDIM) / 32, 1), blk>>>(
        w_out, woh, wol, N_HEADS * HDIM, D_MODEL);

    // 1. projections (split-bf16 tensor-core GEMM)
    cudaFuncSetAttribute(gemm_bf16_kernel, cudaFuncAttributeMaxDynamicSharedMemorySize, GEMM_SMEM);
    gemm_bf16_kernel<<<dim3(T_SEQ / 128, HDIM / 128, 16), blk, GEMM_SMEM>>>(
        xh, xl, wqh, wql, gq, D_MODEL, (size_t)HDIM * D_MODEL, N_HEADS * HDIM, HDIM);
    gemm_bf16_kernel<<<dim3(T_SEQ / 128, HDIM / 128, 16), blk, GEMM_SMEM>>>(
        xh, xl, wkvh, wkvl, gkv, D_MODEL, (size_t)HDIM * D_MODEL, 16 * HDIM, HDIM);

    // 2. norms + rope
    norm_rope_q_kernel <<<(T_SEQ * N_HEADS) / 8, blk>>>(q_scale, segpos);
    norm_rope_kv_kernel<<<(T_SEQ * 16) / 8,      blk>>>(k_scale, segpos);

    // 3. attention (writes enc bf16 hi/lo planes)
    cudaFuncSetAttribute(attn_kernel, cudaFuncAttributeMaxDynamicSharedMemorySize,
                         ATTN_SMEM_FLOATS * 4);
    attn_kernel<<<dim3(T_SEQ / 64, N_HEADS), blk, ATTN_SMEM_FLOATS * 4>>>();

    // 4. output projection (split-bf16)
    gemm_bf16_kernel<<<dim3(T_SEQ / 128, D_MODEL / 128, 1), blk, GEMM_SMEM>>>(
        ench, encl, woh, wol, out, N_HEADS * HDIM, 0, D_MODEL, 0);
}